// round 12
// baseline (speedup 1.0000x reference)
#include <cuda_runtime.h>
#include <cuda_bf16.h>
#include <stdint.h>

// Problem constants: shape (16, 1, 320, 320) fp32, two tensors (pred, target)
#define NIMG   16
#define H      320
#define W      320
#define W2     160             // pixel-pairs per row
#define WPR    10              // 32-bit words per row (320/32)
#define NPIX   (NIMG * H * W)  // 1,638,400
#define NROWS  (NIMG * H)      // 5,120
#define SENT   0x7FFF
#define SENT2  (SENT * SENT)
#define CAPQ   0x3FFF          // saturation cap for stored squared distances
#define BIGF   1e12f
#define SW     4               // strip width in pairs (8 pixels)
#define NSTRIP (W2 / SW)       // 40 strips per image
#define GRID   (NIMG * NSTRIP) // 640 blocks; co-residency: 5 blk/SM max
#define TPAIRS (H * SW)        // 1280 pairs per strip tile

// Scratch (static device globals — no allocation).
// g_D  [p]: per tensor halfword: class<<15 | exact horiz dist to opposite class
// g_Dsq[p]: per tensor halfword: class<<15 | min(dist^2, CAPQ)
__device__ __align__(256) uint32_t g_D[NPIX];
__device__ __align__(256) uint32_t g_Dsq[NPIX];
__device__ double            g_part[GRID];
__device__ unsigned          g_cnt0 = 0, g_cnt1 = 0;       // self-reset via atomicInc wrap
__device__ volatile unsigned g_sense0 = 0, g_sense1 = 0;   // flips once per launch

// ---------------------------------------------------------------------------
// Exact horizontal distance to nearest opposite-class bit; branchless 64-bit
// window covers d<=32 (overwhelmingly common), rare multi-word scan fallback.
__device__ __forceinline__ int nearest_dist64(const uint32_t* wr, int j, int L,
                                              uint32_t pol) {
    uint32_t cj   = wr[j] ^ pol;
    uint32_t cjm1 = (j > 0)       ? (wr[j - 1] ^ pol) : 0u;
    uint32_t cjp1 = (j < WPR - 1) ? (wr[j + 1] ^ pol) : 0u;

    uint64_t winL = ((uint64_t)cj << 32) | cjm1;
    int pos = 32 + L;
    uint64_t mlow = winL & ((2ull << pos) - 1ull);
    int dl;
    if (mlow) {
        dl = pos - 63 + __clzll((long long)mlow);
    } else {
        dl = SENT;
        for (int k2 = j - 2; k2 >= 0; --k2) {          // rare
            uint32_t mm = wr[k2] ^ pol;
            if (mm) { dl = j * 32 + L - (k2 * 32 + 31 - __clz(mm)); break; }
        }
    }
    uint64_t winR = ((uint64_t)cjp1 << 32) | cj;
    uint64_t mhigh = winR & (~0ull << L);
    int dr;
    if (mhigh) {
        dr = __ffsll((long long)mhigh) - 1 - L;
    } else {
        dr = SENT;
        for (int k2 = j + 2; k2 < WPR; ++k2) {         // rare
            uint32_t mm = wr[k2] ^ pol;
            if (mm) { dr = k2 * 32 + (__ffs(mm) - 1) - (j * 32 + L); break; }
        }
    }
    return min(min(dl, dr), SENT);
}

// ---------------------------------------------------------------------------
// Exact per-pixel fallback (cold; only when SIMD result may have saturated).
__device__ __noinline__ float fallback_pixel(int idx, int y) {
    uint32_t own = g_D[idx];
    uint32_t c0 = (own >> 15) & 1u;
    uint32_t c1 = (own >> 31) & 1u;
    int d;
    d = (int)(own & 0x7FFFu);         int b0 = d * d;
    d = (int)((own >> 16) & 0x7FFFu); int b1 = d * d;
    for (int dy = 1; dy < H; ++dy) {
        int dy2 = dy * dy;
        if (dy2 >= b0 && dy2 >= b1) break;
        if (y >= dy) {
            uint32_t v = g_D[idx - dy * W];
            int a0 = (((v >> 15) & 1u) == c0) ? (int)(v & 0x7FFFu) : 0;
            int a1 = (((v >> 31) & 1u) == c1) ? (int)((v >> 16) & 0x7FFFu) : 0;
            b0 = min(b0, dy2 + a0 * a0);
            b1 = min(b1, dy2 + a1 * a1);
        }
        if (y + dy < H) {
            uint32_t v = g_D[idx + dy * W];
            int a0 = (((v >> 15) & 1u) == c0) ? (int)(v & 0x7FFFu) : 0;
            int a1 = (((v >> 31) & 1u) == c1) ? (int)((v >> 16) & 0x7FFFu) : 0;
            b0 = min(b0, dy2 + a0 * a0);
            b1 = min(b1, dy2 + a1 * a1);
        }
    }
    float f0 = (b0 >= SENT2) ? (c0 ? BIGF : 0.f) : (float)b0;
    float f1 = (b1 >= SENT2) ? (c1 ? BIGF : 0.f) : (float)b1;
    return f0 + f1;
}

// ---------------------------------------------------------------------------
__global__ void __launch_bounds__(256, 5)
k_fused(const float* __restrict__ pred, const float* __restrict__ targ,
        float* __restrict__ out) {
    const int tid  = threadIdx.x;
    const int bid  = blockIdx.x;
    const int warp = tid >> 5;
    const int L    = tid & 31;

    // Read barrier senses BEFORE any work.
    const unsigned s0 = g_sense0;
    const unsigned s1 = g_sense1;

    // Phase B column-strip tile (10.25KB). Phase A aliases its head (640B)
    // for row bit-words — safe: grid barrier separates the phases.
    __shared__ uint2 tile[TPAIRS];
    uint32_t (*srow)[2][WPR] = (uint32_t(*)[2][WPR])tile;

    // ---------------- Phase A: horizontal pass, ONE row per warp ----------
    {
        int row = bid * 8 + warp;            // 640*8 = 5120 rows exact
        int base = row * W;
        uint32_t* sp = &srow[warp][0][0];
        uint32_t* st = &srow[warp][1][0];
        for (int j = 0; j < WPR; ++j) {
            float p  = pred[base + j * 32 + L];
            float tt = targ[base + j * 32 + L];
            uint32_t bp = __ballot_sync(0xFFFFFFFFu, p > 0.5f);
            uint32_t bt = __ballot_sync(0xFFFFFFFFu, tt > 0.5f);
            if (L == 0) { sp[j] = bp; st[j] = bt; }
        }
        __syncwarp();
        for (int j = 0; j < WPR; ++j) {
            uint32_t c0 = (sp[j] >> L) & 1u;
            uint32_t c1 = (st[j] >> L) & 1u;
            int d0 = nearest_dist64(sp, j, L, c0 ? 0xFFFFFFFFu : 0u);
            int d1 = nearest_dist64(st, j, L, c1 ? 0xFFFFFFFFu : 0u);
            int pix = base + j * 32 + L;
            g_D[pix] = (c0 << 15) | (uint32_t)d0 | (c1 << 31) | ((uint32_t)d1 << 16);
            uint32_t q0 = (c0 << 15) | (uint32_t)min(d0 * d0, CAPQ);
            uint32_t q1 = (c1 << 15) | (uint32_t)min(d1 * d1, CAPQ);
            g_Dsq[pix] = q0 | (q1 << 16);
        }
    }

    // ---------------- Grid barrier #1 (sense-reversing, self-resetting) ---
    __syncthreads();
    if (tid == 0) {
        __threadfence();
        unsigned t = atomicInc(&g_cnt0, GRID - 1);
        if (t == GRID - 1) g_sense0 = s0 ^ 1u;
        else while (g_sense0 == s0) __nanosleep(32);
        __threadfence();
    }
    __syncthreads();

    // ---------------- Phase B: smem column-strip vertical pass + loss ------
    const int img   = bid / NSTRIP;
    const int strip = bid - img * NSTRIP;
    const uint2* DQ = (const uint2*)g_Dsq;
    const int gbase = img * H * W2 + strip * SW;

    // stage the strip: fully coalesced, one read per pixel
    for (int idx = tid; idx < TPAIRS; idx += 256) {
        int y = idx >> 2, px = idx & 3;
        tile[idx] = DQ[gbase + y * W2 + px];
    }
    __syncthreads();

    float fsum = 0.f;
#pragma unroll
    for (int k = 0; k < TPAIRS / 256; ++k) {         // 5 pairs per thread
        int idx = k * 256 + tid;
        int y  = idx >> 2;
        int yd = (H - 1) - y;

        uint2 own = tile[idx];
        uint32_t mx = own.x & 0x80008000u;           // query class masks
        uint32_t my = own.y & 0x80008000u;
        uint32_t bx = __vmaxs2(own.x ^ mx, 0u);      // own sat d^2 (<= CAPQ)
        uint32_t by = __vmaxs2(own.y ^ my, 0u);

        // Fixed straight-line chunk dy=1..6 with CLAMPED indices (no checks).
        // Clamped reads re-read row 0/H-1 with larger dy^2 than their true
        // term (already covered at dy=y / dy=yd) => never lowers best below
        // the true minimum. Covers ~97% of warps fully; all 12 LDS batched.
#pragma unroll
        for (int dy = 1; dy <= 6; ++dy) {
            int du = min(dy, y);
            int dd = min(dy, yd);
            uint2 vu = tile[idx - du * SW];
            uint2 vd = tile[idx + dd * SW];
            uint32_t dp = (uint32_t)(dy * dy) * 0x00010001u;
            bx = __vmins2(bx, __vadd2(__vmaxs2(vu.x ^ mx, 0u), dp));
            by = __vmins2(by, __vadd2(__vmaxs2(vu.y ^ my, 0u), dp));
            bx = __vmins2(bx, __vadd2(__vmaxs2(vd.x ^ mx, 0u), dp));
            by = __vmins2(by, __vadd2(__vmaxs2(vd.y ^ my, 0u), dp));
        }

        // Rare tail: 2-dy chunks with shrink checks; dy<=127 => s16 adds
        // can't overflow (127^2 + CAPQ = 32512; 128^2 + CAPQ = 32767).
        uint32_t m2 = __vmaxs2(bx, by);
        int bb = max((int)(m2 >> 16), (int)(m2 & 0xFFFFu));
        for (int dy = 7; dy <= 127 && dy * dy < bb; dy += 2) {
            int dya = dy, dyb = dy + 1;
            uint32_t dpa = (uint32_t)(dya * dya) * 0x00010001u;
            uint32_t dpb = (uint32_t)(dyb * dyb) * 0x00010001u;
            uint2 vua = tile[idx - min(dya, y) * SW];
            uint2 vda = tile[idx + min(dya, yd) * SW];
            uint2 vub = tile[idx - min(dyb, y) * SW];
            uint2 vdb = tile[idx + min(dyb, yd) * SW];
            bx = __vmins2(bx, __vadd2(__vmaxs2(vua.x ^ mx, 0u), dpa));
            by = __vmins2(by, __vadd2(__vmaxs2(vua.y ^ my, 0u), dpa));
            bx = __vmins2(bx, __vadd2(__vmaxs2(vda.x ^ mx, 0u), dpa));
            by = __vmins2(by, __vadd2(__vmaxs2(vda.y ^ my, 0u), dpa));
            bx = __vmins2(bx, __vadd2(__vmaxs2(vub.x ^ mx, 0u), dpb));
            by = __vmins2(by, __vadd2(__vmaxs2(vub.y ^ my, 0u), dpb));
            bx = __vmins2(bx, __vadd2(__vmaxs2(vdb.x ^ mx, 0u), dpb));
            by = __vmins2(by, __vadd2(__vmaxs2(vdb.y ^ my, 0u), dpb));
            m2 = __vmaxs2(bx, by);
            bb = max((int)(m2 >> 16), (int)(m2 & 0xFFFFu));
        }

        int b00 = (int)(bx & 0xFFFFu), b01 = (int)(bx >> 16);
        int b10 = (int)(by & 0xFFFFu), b11 = (int)(by >> 16);

        int gp = gbase + y * W2 + (idx & 3);         // global pair index
        float2 pv = ((const float2*)pred)[gp];
        float2 tv = ((const float2*)targ)[gp];
        float e0 = pv.x - tv.x;
        float e1 = pv.y - tv.y;
        // >= CAPQ => may involve saturation or the dy cap -> exact recompute
        float f0 = (max(b00, b01) >= CAPQ) ? fallback_pixel(2 * gp, y)
                                           : (float)(b00 + b01);
        float f1 = (max(b10, b11) >= CAPQ) ? fallback_pixel(2 * gp + 1, y)
                                           : (float)(b10 + b11);
        fsum += e0 * e0 * f0 + e1 * e1 * f1;
    }

    // block reduce fsum -> double partial
#pragma unroll
    for (int off = 16; off; off >>= 1)
        fsum += __shfl_down_sync(0xFFFFFFFFu, fsum, off);
    __shared__ float ws[8];
    if (L == 0) ws[warp] = fsum;
    __syncthreads();
    if (tid == 0) {
        float v = ws[0];
#pragma unroll
        for (int k = 1; k < 8; ++k) v += ws[k];
        g_part[bid] = (double)v;
    }

    // ---------------- Grid barrier #2 -------------------------------------
    __syncthreads();
    if (tid == 0) {
        __threadfence();
        unsigned t = atomicInc(&g_cnt1, GRID - 1);
        if (t == GRID - 1) g_sense1 = s1 ^ 1u;
        else while (g_sense1 == s1) __nanosleep(32);
        __threadfence();
    }
    __syncthreads();

    // ---------------- Final reduction by block 0 ---------------------------
    if (bid == 0) {
        double acc = 0.0;
        for (int k = tid; k < GRID; k += 256) acc += g_part[k];
#pragma unroll
        for (int off = 16; off; off >>= 1)
            acc += __shfl_down_sync(0xFFFFFFFFu, acc, off);
        __shared__ double wd[8];
        if (L == 0) wd[warp] = acc;
        __syncthreads();
        if (tid == 0) {
            double s = wd[0];
#pragma unroll
            for (int k = 1; k < 8; ++k) s += wd[k];
            out[0] = (float)(s / (double)NPIX);
        }
    }
}

// ---------------------------------------------------------------------------
extern "C" void kernel_launch(void* const* d_in, const int* in_sizes, int n_in,
                              void* d_out, int out_size) {
    const float* pred = (const float*)d_in[0];
    const float* targ = (const float*)d_in[1];
    float* out = (float*)d_out;

    k_fused<<<GRID, 256>>>(pred, targ, out);
}

// round 13
// speedup vs baseline: 1.0307x; 1.0307x over previous
#include <cuda_runtime.h>
#include <cuda_bf16.h>
#include <stdint.h>

// Problem constants: shape (16, 1, 320, 320) fp32, two tensors (pred, target)
#define NIMG   16
#define H      320
#define W      320
#define W2     160             // pixel-pairs per row
#define WPR    10              // 32-bit words per row (320/32)
#define NPIX   (NIMG * H * W)  // 1,638,400
#define NROWS  (NIMG * H)      // 5,120
#define SENT   0x7FFF
#define SENT2  (SENT * SENT)
#define CAPQ   0x3FFF          // saturation cap for stored squared distances
#define BIGF   1e12f
#define SW     2               // strip width in pairs (4 pixels)
#define NSTRIP (W2 / SW)       // 80 strips per image
#define NB2    (NIMG * NSTRIP) // 1280 k_loss blocks
#define TPAIRS (H * SW)        // 640 pairs per strip tile

// Scratch (static device globals — no allocation).
// g_D  [p]: per tensor halfword: class<<15 | exact horiz dist to opposite class
// g_Dsq[p]: per tensor halfword: class<<15 | min(dist^2, CAPQ)
__device__ __align__(256) uint32_t g_D[NPIX];
__device__ __align__(256) uint32_t g_Dsq[NPIX];
__device__ double       g_part[NB2];
__device__ unsigned int g_ticket = 0;    // self-resetting via atomicInc wrap

// ---------------------------------------------------------------------------
// Exact horizontal distance to nearest opposite-class bit; branchless 64-bit
// window covers d<=32 (overwhelmingly common), rare multi-word scan fallback.
__device__ __forceinline__ int nearest_dist64(const uint32_t* wr, int j, int L,
                                              uint32_t pol) {
    uint32_t cj   = wr[j] ^ pol;
    uint32_t cjm1 = (j > 0)       ? (wr[j - 1] ^ pol) : 0u;
    uint32_t cjp1 = (j < WPR - 1) ? (wr[j + 1] ^ pol) : 0u;

    uint64_t winL = ((uint64_t)cj << 32) | cjm1;
    int pos = 32 + L;
    uint64_t mlow = winL & ((2ull << pos) - 1ull);
    int dl;
    if (mlow) {
        dl = pos - 63 + __clzll((long long)mlow);
    } else {
        dl = SENT;
        for (int k2 = j - 2; k2 >= 0; --k2) {          // rare
            uint32_t mm = wr[k2] ^ pol;
            if (mm) { dl = j * 32 + L - (k2 * 32 + 31 - __clz(mm)); break; }
        }
    }
    uint64_t winR = ((uint64_t)cjp1 << 32) | cj;
    uint64_t mhigh = winR & (~0ull << L);
    int dr;
    if (mhigh) {
        dr = __ffsll((long long)mhigh) - 1 - L;
    } else {
        dr = SENT;
        for (int k2 = j + 2; k2 < WPR; ++k2) {         // rare
            uint32_t mm = wr[k2] ^ pol;
            if (mm) { dr = k2 * 32 + (__ffs(mm) - 1) - (j * 32 + L); break; }
        }
    }
    return min(min(dl, dr), SENT);
}

// ---------------------------------------------------------------------------
// Exact per-pixel fallback (cold; only when SIMD result may have saturated).
__device__ __noinline__ float fallback_pixel(int idx, int y) {
    uint32_t own = g_D[idx];
    uint32_t c0 = (own >> 15) & 1u;
    uint32_t c1 = (own >> 31) & 1u;
    int d;
    d = (int)(own & 0x7FFFu);         int b0 = d * d;
    d = (int)((own >> 16) & 0x7FFFu); int b1 = d * d;
    for (int dy = 1; dy < H; ++dy) {
        int dy2 = dy * dy;
        if (dy2 >= b0 && dy2 >= b1) break;
        if (y >= dy) {
            uint32_t v = g_D[idx - dy * W];
            int a0 = (((v >> 15) & 1u) == c0) ? (int)(v & 0x7FFFu) : 0;
            int a1 = (((v >> 31) & 1u) == c1) ? (int)((v >> 16) & 0x7FFFu) : 0;
            b0 = min(b0, dy2 + a0 * a0);
            b1 = min(b1, dy2 + a1 * a1);
        }
        if (y + dy < H) {
            uint32_t v = g_D[idx + dy * W];
            int a0 = (((v >> 15) & 1u) == c0) ? (int)(v & 0x7FFFu) : 0;
            int a1 = (((v >> 31) & 1u) == c1) ? (int)((v >> 16) & 0x7FFFu) : 0;
            b0 = min(b0, dy2 + a0 * a0);
            b1 = min(b1, dy2 + a1 * a1);
        }
    }
    float f0 = (b0 >= SENT2) ? (c0 ? BIGF : 0.f) : (float)b0;
    float f1 = (b1 >= SENT2) ? (c1 ? BIGF : 0.f) : (float)b1;
    return f0 + f1;
}

// ---------------------------------------------------------------------------
// Kernel 1: horizontal pass, one row per warp. 640 blocks x 256.
__global__ void __launch_bounds__(256) k_rows(const float* __restrict__ pred,
                                              const float* __restrict__ targ) {
    const int tid  = threadIdx.x;
    const int warp = tid >> 5;
    const int L    = tid & 31;
    __shared__ uint32_t srow[8][2][WPR];

    int row = blockIdx.x * 8 + warp;        // 640*8 = 5120 rows exact
    int base = row * W;
    uint32_t* sp = &srow[warp][0][0];
    uint32_t* st = &srow[warp][1][0];
    for (int j = 0; j < WPR; ++j) {
        float p  = pred[base + j * 32 + L];
        float tt = targ[base + j * 32 + L];
        uint32_t bp = __ballot_sync(0xFFFFFFFFu, p > 0.5f);
        uint32_t bt = __ballot_sync(0xFFFFFFFFu, tt > 0.5f);
        if (L == 0) { sp[j] = bp; st[j] = bt; }
    }
    __syncwarp();
    for (int j = 0; j < WPR; ++j) {
        uint32_t c0 = (sp[j] >> L) & 1u;
        uint32_t c1 = (st[j] >> L) & 1u;
        int d0 = nearest_dist64(sp, j, L, c0 ? 0xFFFFFFFFu : 0u);
        int d1 = nearest_dist64(st, j, L, c1 ? 0xFFFFFFFFu : 0u);
        int pix = base + j * 32 + L;
        g_D[pix] = (c0 << 15) | (uint32_t)d0 | (c1 << 31) | ((uint32_t)d1 << 16);
        uint32_t q0 = (c0 << 15) | (uint32_t)min(d0 * d0, CAPQ);
        uint32_t q1 = (c1 << 15) | (uint32_t)min(d1 * d1, CAPQ);
        g_Dsq[pix] = q0 | (q1 << 16);
    }
}

// ---------------------------------------------------------------------------
// Kernel 2: smem column-strip vertical pass + loss + ticketed final reduce.
// 1280 blocks x 128 threads; strip = full height x 2 pairs (4 pixels).
__global__ void __launch_bounds__(128) k_loss(const float* __restrict__ pred,
                                              const float* __restrict__ targ,
                                              float* __restrict__ out) {
    const int tid = threadIdx.x;
    const int bid = blockIdx.x;
    const int img   = bid / NSTRIP;
    const int strip = bid - img * NSTRIP;
    const uint2* DQ = (const uint2*)g_Dsq;
    const int gbase = img * H * W2 + strip * SW;

    __shared__ uint2 tile[TPAIRS];          // 5.1 KB
    for (int idx = tid; idx < TPAIRS; idx += 128) {
        tile[idx] = DQ[gbase + (idx >> 1) * W2 + (idx & 1)];
    }
    __syncthreads();

    float fsum = 0.f;
#pragma unroll
    for (int k = 0; k < TPAIRS / 128; ++k) {         // 5 pairs per thread
        int idx = k * 128 + tid;
        int y  = idx >> 1;
        int yd = (H - 1) - y;

        uint2 own = tile[idx];
        uint32_t mx = own.x & 0x80008000u;           // query class masks
        uint32_t my = own.y & 0x80008000u;
        uint32_t bx = __vmaxs2(own.x ^ mx, 0u);      // own sat d^2 (<= CAPQ)
        uint32_t by = __vmaxs2(own.y ^ my, 0u);

        // Straight-line dy=1..4 with CLAMPED indices (no branches). Clamped
        // reads re-read row 0/H-1 with larger dy^2 than their true term
        // (already covered at dy=y / dy=yd) => never lowers best below the
        // true minimum. P(warp needs dy>4 after this) is tiny.
#pragma unroll
        for (int dy = 1; dy <= 4; ++dy) {
            int du = min(dy, y);
            int dd = min(dy, yd);
            uint2 vu = tile[idx - du * SW];
            uint2 vd = tile[idx + dd * SW];
            uint32_t dp = (uint32_t)(dy * dy) * 0x00010001u;
            bx = __vmins2(bx, __vadd2(__vmaxs2(vu.x ^ mx, 0u), dp));
            by = __vmins2(by, __vadd2(__vmaxs2(vu.y ^ my, 0u), dp));
            bx = __vmins2(bx, __vadd2(__vmaxs2(vd.x ^ mx, 0u), dp));
            by = __vmins2(by, __vadd2(__vmaxs2(vd.y ^ my, 0u), dp));
        }

        // Rare tail: 2-dy chunks with shrink checks; dy<=127 => s16 adds
        // can't overflow (127^2 + CAPQ = 32512 < 32768).
        uint32_t m2 = __vmaxs2(bx, by);
        int bb = max((int)(m2 >> 16), (int)(m2 & 0xFFFFu));
        for (int dy = 5; dy <= 127 && dy * dy < bb; dy += 2) {
            int dya = dy, dyb = dy + 1;
            uint32_t dpa = (uint32_t)(dya * dya) * 0x00010001u;
            uint32_t dpb = (uint32_t)(dyb * dyb) * 0x00010001u;
            uint2 vua = tile[idx - min(dya, y) * SW];
            uint2 vda = tile[idx + min(dya, yd) * SW];
            uint2 vub = tile[idx - min(dyb, y) * SW];
            uint2 vdb = tile[idx + min(dyb, yd) * SW];
            bx = __vmins2(bx, __vadd2(__vmaxs2(vua.x ^ mx, 0u), dpa));
            by = __vmins2(by, __vadd2(__vmaxs2(vua.y ^ my, 0u), dpa));
            bx = __vmins2(bx, __vadd2(__vmaxs2(vda.x ^ mx, 0u), dpa));
            by = __vmins2(by, __vadd2(__vmaxs2(vda.y ^ my, 0u), dpa));
            bx = __vmins2(bx, __vadd2(__vmaxs2(vub.x ^ mx, 0u), dpb));
            by = __vmins2(by, __vadd2(__vmaxs2(vub.y ^ my, 0u), dpb));
            bx = __vmins2(bx, __vadd2(__vmaxs2(vdb.x ^ mx, 0u), dpb));
            by = __vmins2(by, __vadd2(__vmaxs2(vdb.y ^ my, 0u), dpb));
            m2 = __vmaxs2(bx, by);
            bb = max((int)(m2 >> 16), (int)(m2 & 0xFFFFu));
        }

        int b00 = (int)(bx & 0xFFFFu), b01 = (int)(bx >> 16);
        int b10 = (int)(by & 0xFFFFu), b11 = (int)(by >> 16);

        int gp = gbase + y * W2 + (idx & 1);         // global pair index
        float2 pv = ((const float2*)pred)[gp];
        float2 tv = ((const float2*)targ)[gp];
        float e0 = pv.x - tv.x;
        float e1 = pv.y - tv.y;
        // >= CAPQ => may involve saturation or the dy cap -> exact recompute
        float f0 = (max(b00, b01) >= CAPQ) ? fallback_pixel(2 * gp, y)
                                           : (float)(b00 + b01);
        float f1 = (max(b10, b11) >= CAPQ) ? fallback_pixel(2 * gp + 1, y)
                                           : (float)(b10 + b11);
        fsum += e0 * e0 * f0 + e1 * e1 * f1;
    }

    // block reduce (4 warps) -> double partial
#pragma unroll
    for (int off = 16; off; off >>= 1)
        fsum += __shfl_down_sync(0xFFFFFFFFu, fsum, off);
    __shared__ float ws[4];
    if ((tid & 31) == 0) ws[tid >> 5] = fsum;
    __syncthreads();
    __shared__ bool isLast;
    if (tid == 0) {
        float v = ws[0] + ws[1] + ws[2] + ws[3];
        g_part[bid] = (double)v;
        __threadfence();
        unsigned int tk = atomicInc(&g_ticket, NB2 - 1);  // wraps to 0 => self-reset
        isLast = (tk == NB2 - 1);
    }
    __syncthreads();

    if (isLast) {
        double acc = 0.0;
        for (int k = tid; k < NB2; k += 128) acc += g_part[k];
#pragma unroll
        for (int off = 16; off; off >>= 1)
            acc += __shfl_down_sync(0xFFFFFFFFu, acc, off);
        __shared__ double wd[4];
        if ((tid & 31) == 0) wd[tid >> 5] = acc;
        __syncthreads();
        if (tid == 0) {
            out[0] = (float)((wd[0] + wd[1] + wd[2] + wd[3]) / (double)NPIX);
        }
    }
}

// ---------------------------------------------------------------------------
extern "C" void kernel_launch(void* const* d_in, const int* in_sizes, int n_in,
                              void* d_out, int out_size) {
    const float* pred = (const float*)d_in[0];
    const float* targ = (const float*)d_in[1];
    float* out = (float*)d_out;

    k_rows<<<640, 256>>>(pred, targ);
    k_loss<<<NB2, 128>>>(pred, targ, out);
}